// round 12
// baseline (speedup 1.0000x reference)
#include <cuda_runtime.h>
#include <cstdint>
#include <math_constants.h>

// NearestEmbed R12: 1-pass tf32 GEMM (packed fragments + cp.async pipeline, R11)
// + margin filter (R8, proven) + exact double-precision rerank + gather.
// score[n,k] = ||e_k||^2 - 2 * x_n . e_k

#define D_DIM 256
#define K_DIM 1024
#define BM 128
#define BN 128
#define THREADS 512
#define NCHUNK 64                       // 8 k-tiles x 8 d-chunks
#define CAP 4096
#define GCAP (2 * 1024 * 1024)
#define N_LAT (64 * 1024)

#define SEC_FLOATS 4096                 // one packed array chunk = 16KB
#define BUF_FLOATS (2 * SEC_FLOATS)     // Ah, Bh = 32KB
#define SMEM_DYN (3 * BUF_FLOATS * 4)   // 98304 bytes

__device__ float g_e2[K_DIM];
__device__ int g_emax_bits;
__device__ float g_xn2[N_LAT];
__device__ float g_pA[512 * 8 * SEC_FLOATS];    // [tile][ch][g][mp][tig] float4 (hi)
__device__ float g_pB[64 * SEC_FLOATS];         // [kt*8+ch][g][n][tig] float2 (hi)
__device__ float g_xT[(size_t)N_LAT * D_DIM];   // [n][d]
__device__ float g_eT[K_DIM * D_DIM];           // [k][d]
__device__ int g_cand[GCAP];
__device__ int g_cand_cnt;
__device__ unsigned long long g_umin[N_LAT];

__device__ __forceinline__ uint32_t to_tf32(float f) {
    uint32_t r;
    asm("cvt.rna.tf32.f32 %0, %1;" : "=r"(r) : "f"(f));
    return r;
}
__device__ __forceinline__ uint32_t smem_u32(const void* p) {
    uint32_t a;
    asm("{ .reg .u64 t; cvta.to.shared.u64 t, %1; cvt.u32.u64 %0, t; }" : "=r"(a) : "l"(p));
    return a;
}
__device__ __forceinline__ void cp16(uint32_t dst, const void* src) {
    asm volatile("cp.async.cg.shared.global [%0], [%1], 16;" :: "r"(dst), "l"(src) : "memory");
}
#define CP_COMMIT() asm volatile("cp.async.commit_group;" ::: "memory")
#define CP_WAIT(N)  asm volatile("cp.async.wait_group %0;" :: "n"(N) : "memory")

__device__ __forceinline__ void mma8(float* c, uint4 a, uint2 b) {
    asm volatile(
        "mma.sync.aligned.m16n8k8.row.col.f32.tf32.tf32.f32 "
        "{%0,%1,%2,%3}, {%4,%5,%6,%7}, {%8,%9}, {%0,%1,%2,%3};"
        : "+f"(c[0]), "+f"(c[1]), "+f"(c[2]), "+f"(c[3])
        : "r"(a.x), "r"(a.y), "r"(a.z), "r"(a.w), "r"(b.x), "r"(b.y));
}

// ---------------- prep kernels ----------------
__global__ void init_kernel() {
    int i = blockIdx.x * blockDim.x + threadIdx.x;
    if (i < N_LAT) g_umin[i] = ~0ULL;
    if (i == 0) g_cand_cnt = 0;
}

__global__ void e2_kernel(const float* __restrict__ emb) {
    int k = blockIdx.x * blockDim.x + threadIdx.x;
    float s = 0.f;
#pragma unroll 8
    for (int d = 0; d < D_DIM; ++d) {
        float v = emb[(size_t)d * K_DIM + k];
        s = fmaf(v, v, s);
    }
    g_e2[k] = s;
    atomicMax(&g_emax_bits, __float_as_int(s));
}

// pack x (hi tf32) into fragment-order A chunks
__global__ void packA_kernel(const float* __restrict__ x) {
    __shared__ float xs[32 * 128];
    const int ch = blockIdx.x;
    const int tile = blockIdx.y;
    const int b = tile >> 3;
    const int hw0 = (tile & 7) << 7;
    const int tid = threadIdx.x;
    const float* xb = x + ((size_t)b * D_DIM + ch * 32) * 1024 + hw0;
#pragma unroll
    for (int i = 0; i < 4; ++i) {
        int f = tid + i * 256;
        int r = f >> 5, q = (f & 31) << 2;
        *(float4*)&xs[r * 128 + q] = *(const float4*)(xb + (size_t)r * 1024 + q);
    }
    __syncthreads();
    float4* dh = (float4*)g_pA + (size_t)(tile * 8 + ch) * 1024;
#pragma unroll
    for (int i = 0; i < 4; ++i) {
        int o = tid + i * 256;                  // [g][mp][tig]
        int tig = o & 3, mp = (o >> 2) & 63, g = o >> 8;
        int k = g * 8 + tig;
        int M0 = ((mp & 0x38) << 1) | (mp & 7);
        float4 h;
        h.x = __uint_as_float(to_tf32(xs[k * 128 + M0]));
        h.y = __uint_as_float(to_tf32(xs[k * 128 + M0 + 8]));
        h.z = __uint_as_float(to_tf32(xs[(k + 4) * 128 + M0]));
        h.w = __uint_as_float(to_tf32(xs[(k + 4) * 128 + M0 + 8]));
        dh[o] = h;
    }
}

// pack emb (hi tf32) into fragment-order B chunks: c = kt*8+ch
__global__ void packB_kernel(const float* __restrict__ emb) {
    const int c = blockIdx.x;
    const int kt = c >> 3, ch = c & 7;
    const int k0 = kt * BN, d0 = ch * 32;
    const int tid = threadIdx.x;
    float2* dh = (float2*)g_pB + (size_t)c * 2048;
#pragma unroll
    for (int i = 0; i < 8; ++i) {
        int o = tid + i * 256;                  // [g][n][tig]
        int tig = o & 3, n = (o >> 2) & 127, g = o >> 9;
        int k = d0 + g * 8 + tig;
        float2 h;
        h.x = __uint_as_float(to_tf32(emb[(size_t)k * K_DIM + k0 + n]));
        h.y = __uint_as_float(to_tf32(emb[(size_t)(k + 4) * K_DIM + k0 + n]));
        dh[o] = h;
    }
}

__global__ void xt_kernel(const float* __restrict__ x) {
    __shared__ float t[32][33];
    const int b = blockIdx.z;
    const int d0 = blockIdx.y * 32;
    const int hw0 = blockIdx.x * 32;
    const int tx = threadIdx.x, ty = threadIdx.y;
#pragma unroll
    for (int i = 0; i < 4; ++i)
        t[ty + i * 8][tx] = x[((size_t)b * D_DIM + d0 + ty + i * 8) * 1024 + hw0 + tx];
    __syncthreads();
#pragma unroll
    for (int i = 0; i < 4; ++i) {
        int n = b * 1024 + hw0 + ty + i * 8;
        g_xT[(size_t)n * D_DIM + d0 + tx] = t[tx][ty + i * 8];
    }
}

__global__ void et_kernel(const float* __restrict__ emb) {
    __shared__ float t[32][33];
    const int d0 = blockIdx.y * 32;
    const int k0 = blockIdx.x * 32;
    const int tx = threadIdx.x, ty = threadIdx.y;
#pragma unroll
    for (int i = 0; i < 4; ++i)
        t[ty + i * 8][tx] = emb[(size_t)(d0 + ty + i * 8) * K_DIM + k0 + tx];
    __syncthreads();
#pragma unroll
    for (int i = 0; i < 4; ++i)
        g_eT[(size_t)(k0 + ty + i * 8) * D_DIM + d0 + tx] = t[tx][ty + i * 8];
}

__global__ void xn2_kernel() {
    int w = (blockIdx.x * blockDim.x + threadIdx.x) >> 5;
    int lane = threadIdx.x & 31;
    const float* r = g_xT + (size_t)w * D_DIM;
    float s = 0.f;
#pragma unroll
    for (int d = lane; d < D_DIM; d += 32) {
        float v = r[d];
        s = fmaf(v, v, s);
    }
#pragma unroll
    for (int off = 16; off > 0; off >>= 1) s += __shfl_xor_sync(0xFFFFFFFFu, s, off);
    if (lane == 0) g_xn2[w] = s;
}

// ---------------- GEMM + filter ----------------
__global__ __launch_bounds__(THREADS, 1)
void vq_mma_kernel() {
    extern __shared__ float sm[];
    __shared__ float e2s[K_DIM];
    __shared__ float redv[BM][4];
    __shared__ float runmin[BM];
    __shared__ float marg[BM];
    __shared__ int cand[CAP];
    __shared__ int cand_cnt;
    __shared__ int flush_base;

    const int tid = threadIdx.x;
    const int wid = tid >> 5;
    const int lane = tid & 31;
    const int gid = lane >> 2;
    const int tig = lane & 3;
    const int wm = wid >> 2;
    const int wn = wid & 3;
    const int mbw = wm * 32;
    const int nbw = wn * 32;
    const uint32_t smb = smem_u32(sm);

    const int tile = blockIdx.x;
    const int n0 = tile * BM;

    auto stage = [&](int c) {
        const uint32_t base = smb + (uint32_t)(c % 3) * (BUF_FLOATS * 4);
        const float* sA = g_pA + (size_t)(tile * 8 + (c & 7)) * SEC_FLOATS;
        const float* sB = g_pB + (size_t)c * SEC_FLOATS;
#pragma unroll
        for (int i = 0; i < 2; ++i) {
            int t = tid + i * THREADS;          // float4 index 0..1023
            cp16(base + t * 16, sA + t * 4);
            cp16(base + SEC_FLOATS * 4 + t * 16, sB + t * 4);
        }
    };

    if (tid == 0) cand_cnt = 0;
    for (int i = tid; i < K_DIM; i += THREADS) e2s[i] = g_e2[i];
    {
        const float semax = sqrtf(__int_as_float(g_emax_bits));
        for (int i = tid; i < BM; i += THREADS) {
            marg[i] = 0.00390625f * sqrtf(g_xn2[n0 + i]) * semax + 4e-3f;
            runmin[i] = CUDART_INF_F;
        }
    }
    __syncthreads();

    float best[4];
#pragma unroll
    for (int s = 0; s < 4; ++s) best[s] = CUDART_INF_F;

    stage(0); CP_COMMIT();
    stage(1); CP_COMMIT();

    float acc[2][4][4];
    const int a0i = (gid + wm * 16) * 4 + tig;
    const int a1i = (gid + 8 + wm * 16) * 4 + tig;
    const int bbase = (nbw + gid) * 4 + tig;

    for (int c = 0; c < NCHUNK; ++c) {
        if ((c & 7) == 0) {
#pragma unroll
            for (int mt = 0; mt < 2; ++mt)
#pragma unroll
                for (int nt = 0; nt < 4; ++nt)
#pragma unroll
                    for (int j = 0; j < 4; ++j) acc[mt][nt][j] = 0.f;
        }

        if (c < NCHUNK - 1) { CP_WAIT(1); } else { CP_WAIT(0); }
        __syncthreads();
        if (c + 2 < NCHUNK) { stage(c + 2); CP_COMMIT(); }

        const float* buf = sm + (c % 3) * BUF_FLOATS;
        const uint4* Ah = (const uint4*)buf;
        const uint2* Bh = (const uint2*)(buf + SEC_FLOATS);

#pragma unroll
        for (int g = 0; g < 4; ++g) {
            uint4 ah0 = Ah[g * 256 + a0i];
            uint4 ah1 = Ah[g * 256 + a1i];
#pragma unroll
            for (int nt = 0; nt < 4; ++nt) {
                uint2 bh = Bh[g * 512 + bbase + nt * 32];
                mma8(acc[0][nt], ah0, bh);
                mma8(acc[1][nt], ah1, bh);
            }
        }

        if ((c & 7) == 7) {
            const int k0 = (c >> 3) * BN;
            // scores in regs; update per-thread running best
#pragma unroll
            for (int mt = 0; mt < 2; ++mt)
#pragma unroll
                for (int nt = 0; nt < 4; ++nt) {
                    const int kc = k0 + nbw + nt * 8 + 2 * tig;
                    acc[mt][nt][0] = fmaf(-2.f, acc[mt][nt][0], e2s[kc]);
                    acc[mt][nt][1] = fmaf(-2.f, acc[mt][nt][1], e2s[kc + 1]);
                    acc[mt][nt][2] = fmaf(-2.f, acc[mt][nt][2], e2s[kc]);
                    acc[mt][nt][3] = fmaf(-2.f, acc[mt][nt][3], e2s[kc + 1]);
                    best[2 * mt] = fminf(best[2 * mt], fminf(acc[mt][nt][0], acc[mt][nt][1]));
                    best[2 * mt + 1] = fminf(best[2 * mt + 1], fminf(acc[mt][nt][2], acc[mt][nt][3]));
                }
            // running-min reduce
#pragma unroll
            for (int s = 0; s < 4; ++s) {
                float v = best[s];
#pragma unroll
                for (int off = 1; off <= 2; off <<= 1)
                    v = fminf(v, __shfl_xor_sync(0xFFFFFFFFu, v, off));
                if (tig == 0) {
                    int row = mbw + (s >> 1) * 16 + gid + (s & 1) * 8;
                    redv[row][wn] = v;
                }
            }
            __syncthreads();
            if (tid < BM)
                runmin[tid] = fminf(fminf(redv[tid][0], redv[tid][1]),
                                    fminf(redv[tid][2], redv[tid][3]));
            __syncthreads();
            // candidate scan (running-min + margin -> superset, safe)
#pragma unroll
            for (int mt = 0; mt < 2; ++mt) {
                const int r0 = mbw + mt * 16 + gid;
                const float t0 = runmin[r0] + marg[r0];
                const float t1 = runmin[r0 + 8] + marg[r0 + 8];
#pragma unroll
                for (int nt = 0; nt < 4; ++nt) {
                    const int kc = k0 + nbw + nt * 8 + 2 * tig;
                    if (acc[mt][nt][0] <= t0) { int p = atomicAdd(&cand_cnt, 1); if (p < CAP) cand[p] = ((n0 + r0) << 10) | kc; }
                    if (acc[mt][nt][1] <= t0) { int p = atomicAdd(&cand_cnt, 1); if (p < CAP) cand[p] = ((n0 + r0) << 10) | (kc + 1); }
                    if (acc[mt][nt][2] <= t1) { int p = atomicAdd(&cand_cnt, 1); if (p < CAP) cand[p] = ((n0 + r0 + 8) << 10) | kc; }
                    if (acc[mt][nt][3] <= t1) { int p = atomicAdd(&cand_cnt, 1); if (p < CAP) cand[p] = ((n0 + r0 + 8) << 10) | (kc + 1); }
                }
            }
        }
    }
    __syncthreads();

    // flush candidates to global list
    int cnt = cand_cnt;
    if (cnt > CAP) cnt = CAP;
    if (tid == 0) flush_base = atomicAdd(&g_cand_cnt, cnt);
    __syncthreads();
    int base = flush_base;
    for (int i = tid; i < cnt; i += THREADS)
        if (base + i < GCAP) g_cand[base + i] = cand[i];
}

// ---------------- exact re-rank (warp per candidate) ----------------
__global__ void rerank_kernel() {
    const int nwarp = (gridDim.x * blockDim.x) >> 5;
    const int w = (blockIdx.x * blockDim.x + threadIdx.x) >> 5;
    const int lane = threadIdx.x & 31;
    int cnt = g_cand_cnt;
    if (cnt > GCAP) cnt = GCAP;

    for (int i = w; i < cnt; i += nwarp) {
        int c = g_cand[i];
        int n = c >> 10;
        int k = c & 1023;
        const float4* xr = (const float4*)(g_xT + (size_t)n * D_DIM);
        const float4* er = (const float4*)(g_eT + (size_t)k * D_DIM);
        double s = 0.0;
#pragma unroll
        for (int j = 0; j < 2; ++j) {
            float4 xv = xr[lane + j * 32];
            float4 ev = er[lane + j * 32];
            s = fma((double)ev.x, (double)ev.x - 2.0 * (double)xv.x, s);
            s = fma((double)ev.y, (double)ev.y - 2.0 * (double)xv.y, s);
            s = fma((double)ev.z, (double)ev.z - 2.0 * (double)xv.z, s);
            s = fma((double)ev.w, (double)ev.w - 2.0 * (double)xv.w, s);
        }
#pragma unroll
        for (int off = 16; off > 0; off >>= 1)
            s += __shfl_xor_sync(0xFFFFFFFFu, s, off);
        if (lane == 0) {
            long long bits = __double_as_longlong(s);
            unsigned long long u = (unsigned long long)bits;
            u ^= (bits < 0) ? 0xFFFFFFFFFFFFFFFFULL : 0x8000000000000000ULL;
            unsigned long long v = (u & ~1023ULL) | (unsigned long long)k;
            atomicMin(&g_umin[n], v);
        }
    }
}

// ---------------- gather / output ----------------
__global__ void gather_kernel(const float* __restrict__ emb, float* __restrict__ out,
                              float* __restrict__ idx_out, int has_idx) {
    __shared__ int kwin[BM];
    const int tid = threadIdx.x;
    const int n0 = blockIdx.x * BM;
    const int b = n0 >> 10;
    const int hw0 = n0 & 1023;
    if (tid < BM) {
        int k = (int)(g_umin[n0 + tid] & 1023ULL);
        kwin[tid] = k;
        if (has_idx) idx_out[n0 + tid] = (float)k;
    }
    __syncthreads();
    for (int r = tid; r < D_DIM * BM; r += 256) {
        int d = r >> 7;
        int m = r & (BM - 1);
        out[((size_t)b * D_DIM + d) * 1024 + hw0 + m] = emb[(size_t)d * K_DIM + kwin[m]];
    }
}

extern "C" void kernel_launch(void* const* d_in, const int* in_sizes, int n_in,
                              void* d_out, int out_size) {
    const float* x = (const float*)d_in[0];    // (64,256,32,32)
    const float* emb = (const float*)d_in[1];  // (256,1024)
    float* out = (float*)d_out;

    const int n_img = 64 * 256 * 32 * 32;
    const int n_lat = 64 * 32 * 32;
    float* idx_out = nullptr;
    int has_idx = 0;
    if (out_size >= n_img + n_lat) {
        idx_out = out + n_img;
        has_idx = 1;
    }

    cudaFuncSetAttribute(vq_mma_kernel, cudaFuncAttributeMaxDynamicSharedMemorySize, SMEM_DYN);

    init_kernel<<<N_LAT / 256, 256>>>();
    e2_kernel<<<4, 256>>>(emb);
    packA_kernel<<<dim3(8, 512), 256>>>(x);
    packB_kernel<<<64, 256>>>(emb);
    xt_kernel<<<dim3(32, 8, 64), dim3(32, 8)>>>(x);
    et_kernel<<<dim3(32, 8, 1), dim3(32, 8)>>>(emb);
    xn2_kernel<<<N_LAT / 8, 256>>>();
    vq_mma_kernel<<<512, THREADS, SMEM_DYN>>>();
    rerank_kernel<<<1024, 256>>>();
    gather_kernel<<<512, 256>>>(emb, out, idx_out, has_idx);
}

// round 13
// speedup vs baseline: 2.5637x; 2.5637x over previous
#include <cuda_runtime.h>
#include <cuda_fp16.h>
#include <cstdint>
#include <math_constants.h>

// NearestEmbed via mma.sync m16n8k16 fp16 (3-pass hi/lo split) + fused argmin.
// R13 = R11 pipeline (packed fragments, cp.async x3 buffers, 1 barrier/chunk)
// with fp16 MMA: 48 MMA + 24 LDS per chunk (was 96 + 48 with tf32).
// score[n,k] = ||e_k||^2 - 2 * x_n . e_k
// dot = xh.eh + xh.el + xl.eh  (fp16 split, fp32 accumulate; xl.el ~ 2^-22)

#define D_DIM 256
#define K_DIM 1024
#define BM 128
#define BN 128
#define THREADS 512
#define NCHUNK 64                       // 8 k-tiles x 8 d-chunks

#define SEC_BYTES 8192                  // one packed fp16 array chunk
#define BUF_BYTES (4 * SEC_BYTES)       // Ah, Al, Bh, Bl = 32KB
#define SMEM_DYN (3 * BUF_BYTES)        // 98304 bytes

__device__ float g_e2[K_DIM];
__device__ uint32_t g_pAh[512 * 8 * 2048];   // [tile][ch][g][mp][tig] uint4 of fp16x2
__device__ uint32_t g_pAl[512 * 8 * 2048];
__device__ uint32_t g_pBh[64 * 2048];        // [c][g][n][tig] uint2 of fp16x2
__device__ uint32_t g_pBl[64 * 2048];

__device__ __forceinline__ uint32_t smem_u32(const void* p) {
    uint32_t a;
    asm("{ .reg .u64 t; cvta.to.shared.u64 t, %1; cvt.u32.u64 %0, t; }" : "=r"(a) : "l"(p));
    return a;
}
__device__ __forceinline__ void cp16(uint32_t dst, const void* src) {
    asm volatile("cp.async.cg.shared.global [%0], [%1], 16;" :: "r"(dst), "l"(src) : "memory");
}
#define CP_COMMIT() asm volatile("cp.async.commit_group;" ::: "memory")
#define CP_WAIT(N)  asm volatile("cp.async.wait_group %0;" :: "n"(N) : "memory")

__device__ __forceinline__ void mma16(float* c, uint4 a, uint2 b) {
    asm volatile(
        "mma.sync.aligned.m16n8k16.row.col.f32.f16.f16.f32 "
        "{%0,%1,%2,%3}, {%4,%5,%6,%7}, {%8,%9}, {%0,%1,%2,%3};"
        : "+f"(c[0]), "+f"(c[1]), "+f"(c[2]), "+f"(c[3])
        : "r"(a.x), "r"(a.y), "r"(a.z), "r"(a.w), "r"(b.x), "r"(b.y));
}

// split v into hi/lo fp16, return packed pair makers
__device__ __forceinline__ void split2(float v0, float v1, uint32_t& hi, uint32_t& lo) {
    __half h0 = __float2half_rn(v0);
    __half h1 = __float2half_rn(v1);
    __half l0 = __float2half_rn(v0 - __half2float(h0));
    __half l1 = __float2half_rn(v1 - __half2float(h1));
    hi = (uint32_t)__half_as_ushort(h0) | ((uint32_t)__half_as_ushort(h1) << 16);
    lo = (uint32_t)__half_as_ushort(l0) | ((uint32_t)__half_as_ushort(l1) << 16);
}

// ---------------- prep kernels ----------------
__global__ void e2_kernel(const float* __restrict__ emb) {
    int k = blockIdx.x * blockDim.x + threadIdx.x;
    float s = 0.f;
#pragma unroll 8
    for (int d = 0; d < D_DIM; ++d) {
        float v = emb[(size_t)d * K_DIM + k];
        s = fmaf(v, v, s);
    }
    g_e2[k] = s;
}

// pack x into fp16 hi/lo fragment-order A chunks
__global__ void packA_kernel(const float* __restrict__ x) {
    __shared__ float xs[32 * 128];
    const int ch = blockIdx.x;
    const int tile = blockIdx.y;
    const int b = tile >> 3;
    const int hw0 = (tile & 7) << 7;
    const int tid = threadIdx.x;
    const float* xb = x + ((size_t)b * D_DIM + ch * 32) * 1024 + hw0;
#pragma unroll
    for (int i = 0; i < 4; ++i) {
        int f = tid + i * 256;
        int r = f >> 5, q = (f & 31) << 2;
        *(float4*)&xs[r * 128 + q] = *(const float4*)(xb + (size_t)r * 1024 + q);
    }
    __syncthreads();
    uint4* dh = (uint4*)g_pAh + (size_t)(tile * 8 + ch) * 512;
    uint4* dl = (uint4*)g_pAl + (size_t)(tile * 8 + ch) * 512;
#pragma unroll
    for (int i = 0; i < 2; ++i) {
        int o = tid + i * 256;                  // [g][mp][tig], 512 total
        int tig = o & 3, mp = (o >> 2) & 63, g = o >> 8;
        int k2 = g * 16 + 2 * tig;
        int M0 = ((mp & 0x38) << 1) | (mp & 7);
        uint4 h, l;
        split2(xs[k2 * 128 + M0],       xs[(k2 + 1) * 128 + M0],       h.x, l.x);
        split2(xs[k2 * 128 + M0 + 8],   xs[(k2 + 1) * 128 + M0 + 8],   h.y, l.y);
        split2(xs[(k2 + 8) * 128 + M0],     xs[(k2 + 9) * 128 + M0],     h.z, l.z);
        split2(xs[(k2 + 8) * 128 + M0 + 8], xs[(k2 + 9) * 128 + M0 + 8], h.w, l.w);
        dh[o] = h;
        dl[o] = l;
    }
}

// pack emb into fp16 hi/lo fragment-order B chunks: c = kt*8+ch
__global__ void packB_kernel(const float* __restrict__ emb) {
    const int c = blockIdx.x;
    const int kt = c >> 3, ch = c & 7;
    const int k0 = kt * BN, d0 = ch * 32;
    const int tid = threadIdx.x;
    uint2* dh = (uint2*)g_pBh + (size_t)c * 1024;
    uint2* dl = (uint2*)g_pBl + (size_t)c * 1024;
#pragma unroll
    for (int i = 0; i < 4; ++i) {
        int o = tid + i * 256;                  // [g][n][tig], 1024 total
        int tig = o & 3, n = (o >> 2) & 127, g = o >> 9;
        int k2 = d0 + g * 16 + 2 * tig;
        uint2 h, l;
        split2(emb[(size_t)k2 * K_DIM + k0 + n],       emb[(size_t)(k2 + 1) * K_DIM + k0 + n],       h.x, l.x);
        split2(emb[(size_t)(k2 + 8) * K_DIM + k0 + n], emb[(size_t)(k2 + 9) * K_DIM + k0 + n],       h.y, l.y);
        dh[o] = h;
        dl[o] = l;
    }
}

// ---------------- main kernel ----------------
__global__ __launch_bounds__(THREADS, 1)
void vq_mma_kernel(const float* __restrict__ emb, float* __restrict__ out,
                   float* __restrict__ idx_out, int has_idx) {
    extern __shared__ char smc[];
    __shared__ float e2s[K_DIM];
    __shared__ float redv[BM][4];
    __shared__ int redi[BM][4];
    __shared__ int idx_s[BM];

    const int tid = threadIdx.x;
    const int wid = tid >> 5;
    const int lane = tid & 31;
    const int gid = lane >> 2;
    const int tig = lane & 3;
    const int wm = wid >> 2;
    const int wn = wid & 3;
    const int mbw = wm * 32;
    const int nbw = wn * 32;
    const uint32_t smb = smem_u32(smc);

    const int tile = blockIdx.x;
    const int n0 = tile * BM;
    const int b = n0 >> 10;
    const int hw0 = n0 & 1023;

    // staging: chunk c -> buffer c%3, pure linear 16B copies, 4 per thread
    auto stage = [&](int c) {
        const uint32_t base = smb + (uint32_t)(c % 3) * BUF_BYTES;
        const uint4* sAh = (const uint4*)g_pAh + (size_t)(tile * 8 + (c & 7)) * 512;
        const uint4* sAl = (const uint4*)g_pAl + (size_t)(tile * 8 + (c & 7)) * 512;
        const uint4* sBh = (const uint4*)g_pBh + (size_t)c * 512;
        const uint4* sBl = (const uint4*)g_pBl + (size_t)c * 512;
        cp16(base + tid * 16, sAh + tid);
        cp16(base + SEC_BYTES + tid * 16, sAl + tid);
        cp16(base + 2 * SEC_BYTES + tid * 16, sBh + tid);
        cp16(base + 3 * SEC_BYTES + tid * 16, sBl + tid);
    };

    for (int i = tid; i < K_DIM; i += THREADS) e2s[i] = g_e2[i];

    float best[4];
    int bidx[4];
#pragma unroll
    for (int s = 0; s < 4; ++s) { best[s] = CUDART_INF_F; bidx[s] = 0; }

    stage(0); CP_COMMIT();
    stage(1); CP_COMMIT();

    float acc[2][4][4];
    const int a0i = (gid + wm * 16) * 4 + tig;       // mt=0 fragment index
    const int a1i = (gid + 8 + wm * 16) * 4 + tig;   // mt=1
    const int bbase = (nbw + gid) * 4 + tig;

    for (int c = 0; c < NCHUNK; ++c) {
        if ((c & 7) == 0) {
#pragma unroll
            for (int mt = 0; mt < 2; ++mt)
#pragma unroll
                for (int nt = 0; nt < 4; ++nt)
#pragma unroll
                    for (int j = 0; j < 4; ++j) acc[mt][nt][j] = 0.f;
        }

        if (c < NCHUNK - 1) { CP_WAIT(1); } else { CP_WAIT(0); }
        __syncthreads();
        if (c + 2 < NCHUNK) { stage(c + 2); CP_COMMIT(); }

        const char* buf = smc + (c % 3) * BUF_BYTES;
        const uint4* Ah = (const uint4*)buf;
        const uint4* Al = (const uint4*)(buf + SEC_BYTES);
        const uint2* Bh = (const uint2*)(buf + 2 * SEC_BYTES);
        const uint2* Bl = (const uint2*)(buf + 3 * SEC_BYTES);

#pragma unroll
        for (int g = 0; g < 2; ++g) {
            uint4 ah0 = Ah[g * 256 + a0i];
            uint4 ah1 = Ah[g * 256 + a1i];
            uint4 al0 = Al[g * 256 + a0i];
            uint4 al1 = Al[g * 256 + a1i];
#pragma unroll
            for (int nt = 0; nt < 4; ++nt) {
                uint2 bh = Bh[g * 512 + bbase + nt * 32];
                uint2 bl = Bl[g * 512 + bbase + nt * 32];
                mma16(acc[0][nt], ah0, bh);
                mma16(acc[0][nt], ah0, bl);
                mma16(acc[0][nt], al0, bh);
                mma16(acc[1][nt], ah1, bh);
                mma16(acc[1][nt], ah1, bl);
                mma16(acc[1][nt], al1, bh);
            }
        }

        if ((c & 7) == 7) {
            // fused argmin epilogue for k-tile kt = c>>3 (registers only)
            const int k0 = (c >> 3) * BN;
#pragma unroll
            for (int mt = 0; mt < 2; ++mt) {
#pragma unroll
                for (int nt = 0; nt < 4; ++nt) {
                    const int kc = k0 + nbw + nt * 8 + 2 * tig;
                    const float e20 = e2s[kc], e21 = e2s[kc + 1];
                    float s0 = fmaf(-2.f, acc[mt][nt][0], e20);
                    float s1 = fmaf(-2.f, acc[mt][nt][1], e21);
                    float s2 = fmaf(-2.f, acc[mt][nt][2], e20);
                    float s3 = fmaf(-2.f, acc[mt][nt][3], e21);
                    if (s0 < best[2 * mt]) { best[2 * mt] = s0; bidx[2 * mt] = kc; }
                    if (s1 < best[2 * mt]) { best[2 * mt] = s1; bidx[2 * mt] = kc + 1; }
                    if (s2 < best[2 * mt + 1]) { best[2 * mt + 1] = s2; bidx[2 * mt + 1] = kc; }
                    if (s3 < best[2 * mt + 1]) { best[2 * mt + 1] = s3; bidx[2 * mt + 1] = kc + 1; }
                }
            }
        }
    }

    // reduce across the 4 lanes of each quad (same rows, different cols)
#pragma unroll
    for (int s = 0; s < 4; ++s) {
        float v = best[s];
        int ix = bidx[s];
#pragma unroll
        for (int off = 1; off <= 2; off <<= 1) {
            float v2 = __shfl_xor_sync(0xFFFFFFFFu, v, off);
            int i2 = __shfl_xor_sync(0xFFFFFFFFu, ix, off);
            if (v2 < v || (v2 == v && i2 < ix)) { v = v2; ix = i2; }
        }
        if (tig == 0) {
            int row = mbw + (s >> 1) * 16 + gid + (s & 1) * 8;
            redv[row][wn] = v;
            redi[row][wn] = ix;
        }
    }
    __syncthreads();
    if (tid < BM) {
        float bv = redv[tid][0];
        int bi = redi[tid][0];
#pragma unroll
        for (int t = 1; t < 4; ++t) {
            float v = redv[tid][t];
            int id = redi[tid][t];
            if (v < bv || (v == bv && id < bi)) { bv = v; bi = id; }
        }
        idx_s[tid] = bi;
        if (has_idx) idx_out[n0 + tid] = (float)bi;
    }
    __syncthreads();

    // gather nearest code (exact fp32), scatter to (B,D,H,W)
    for (int r = tid; r < D_DIM * BM; r += THREADS) {
        int d = r >> 7;
        int m = r & (BM - 1);
        out[((size_t)b * D_DIM + d) * 1024 + hw0 + m] = emb[(size_t)d * K_DIM + idx_s[m]];
    }
}

extern "C" void kernel_launch(void* const* d_in, const int* in_sizes, int n_in,
                              void* d_out, int out_size) {
    const float* x = (const float*)d_in[0];    // (64,256,32,32)
    const float* emb = (const float*)d_in[1];  // (256,1024)
    float* out = (float*)d_out;

    const int n_img = 64 * 256 * 32 * 32;
    const int n_lat = 64 * 32 * 32;
    float* idx_out = nullptr;
    int has_idx = 0;
    if (out_size >= n_img + n_lat) {
        idx_out = out + n_img;
        has_idx = 1;
    }

    cudaFuncSetAttribute(vq_mma_kernel, cudaFuncAttributeMaxDynamicSharedMemorySize, SMEM_DYN);

    e2_kernel<<<4, 256>>>(emb);
    packA_kernel<<<dim3(8, 512), 256>>>(x);
    packB_kernel<<<64, 256>>>(emb);
    vq_mma_kernel<<<512, THREADS, SMEM_DYN>>>(emb, out, idx_out, has_idx);
}

// round 14
// speedup vs baseline: 3.1416x; 1.2254x over previous
#include <cuda_runtime.h>
#include <cuda_fp16.h>
#include <cstdint>
#include <math_constants.h>

// NearestEmbed via mma.sync m16n8k16 fp16 (3-pass hi/lo split) + fused argmin.
// R14 = R13 with 2 CTAs/SM: 256 threads, CTA tile 64x128, 1024 CTAs ->
// barrier/epilogue stalls of one CTA overlap with the other CTA's MMAs.
// score[n,k] = ||e_k||^2 - 2 * x_n . e_k
// dot = xh.eh + xh.el + xl.eh  (fp16 split, fp32 accumulate; xl.el ~ 2^-22)

#define D_DIM 256
#define K_DIM 1024
#define BMC 64                          // latents per CTA
#define THREADS 256
#define NCHUNK 64                       // 8 k-tiles x 8 d-chunks

#define A_BYTES 4096                    // A-half hi (64 lat x 32 d fp16)
#define B_BYTES 8192                    // B hi (128 codes x 32 d fp16)
#define BUF_BYTES (2 * A_BYTES + 2 * B_BYTES)   // 24576
#define SMEM_DYN (3 * BUF_BYTES)        // 73728

__device__ float g_e2[K_DIM];
__device__ uint32_t g_pAh[512 * 8 * 2048];   // [tile128][ch][g][mp][tig] fp16x2
__device__ uint32_t g_pAl[512 * 8 * 2048];
__device__ uint32_t g_pBh[64 * 2048];        // [c][g][n][tig] fp16x2
__device__ uint32_t g_pBl[64 * 2048];

__device__ __forceinline__ uint32_t smem_u32(const void* p) {
    uint32_t a;
    asm("{ .reg .u64 t; cvta.to.shared.u64 t, %1; cvt.u32.u64 %0, t; }" : "=r"(a) : "l"(p));
    return a;
}
__device__ __forceinline__ void cp16(uint32_t dst, const void* src) {
    asm volatile("cp.async.cg.shared.global [%0], [%1], 16;" :: "r"(dst), "l"(src) : "memory");
}
#define CP_COMMIT() asm volatile("cp.async.commit_group;" ::: "memory")
#define CP_WAIT(N)  asm volatile("cp.async.wait_group %0;" :: "n"(N) : "memory")

__device__ __forceinline__ void mma16(float* c, uint4 a, uint2 b) {
    asm volatile(
        "mma.sync.aligned.m16n8k16.row.col.f32.f16.f16.f32 "
        "{%0,%1,%2,%3}, {%4,%5,%6,%7}, {%8,%9}, {%0,%1,%2,%3};"
        : "+f"(c[0]), "+f"(c[1]), "+f"(c[2]), "+f"(c[3])
        : "r"(a.x), "r"(a.y), "r"(a.z), "r"(a.w), "r"(b.x), "r"(b.y));
}

__device__ __forceinline__ void split2(float v0, float v1, uint32_t& hi, uint32_t& lo) {
    __half h0 = __float2half_rn(v0);
    __half h1 = __float2half_rn(v1);
    __half l0 = __float2half_rn(v0 - __half2float(h0));
    __half l1 = __float2half_rn(v1 - __half2float(h1));
    hi = (uint32_t)__half_as_ushort(h0) | ((uint32_t)__half_as_ushort(h1) << 16);
    lo = (uint32_t)__half_as_ushort(l0) | ((uint32_t)__half_as_ushort(l1) << 16);
}

// ---------------- prep kernels ----------------
__global__ void e2_kernel(const float* __restrict__ emb) {
    int k = blockIdx.x * blockDim.x + threadIdx.x;
    float s = 0.f;
#pragma unroll 8
    for (int d = 0; d < D_DIM; ++d) {
        float v = emb[(size_t)d * K_DIM + k];
        s = fmaf(v, v, s);
    }
    g_e2[k] = s;
}

// pack x into fp16 hi/lo fragment-order A chunks (per 128-latent tile)
__global__ void packA_kernel(const float* __restrict__ x) {
    __shared__ float xs[32 * 128];
    const int ch = blockIdx.x;
    const int tile = blockIdx.y;
    const int b = tile >> 3;
    const int hw0 = (tile & 7) << 7;
    const int tid = threadIdx.x;
    const float* xb = x + ((size_t)b * D_DIM + ch * 32) * 1024 + hw0;
#pragma unroll
    for (int i = 0; i < 4; ++i) {
        int f = tid + i * 256;
        int r = f >> 5, q = (f & 31) << 2;
        *(float4*)&xs[r * 128 + q] = *(const float4*)(xb + (size_t)r * 1024 + q);
    }
    __syncthreads();
    uint4* dh = (uint4*)g_pAh + (size_t)(tile * 8 + ch) * 512;
    uint4* dl = (uint4*)g_pAl + (size_t)(tile * 8 + ch) * 512;
#pragma unroll
    for (int i = 0; i < 2; ++i) {
        int o = tid + i * 256;                  // [g][mp][tig], 512 total
        int tig = o & 3, mp = (o >> 2) & 63, g = o >> 8;
        int k2 = g * 16 + 2 * tig;
        int M0 = ((mp & 0x38) << 1) | (mp & 7);
        uint4 h, l;
        split2(xs[k2 * 128 + M0],       xs[(k2 + 1) * 128 + M0],       h.x, l.x);
        split2(xs[k2 * 128 + M0 + 8],   xs[(k2 + 1) * 128 + M0 + 8],   h.y, l.y);
        split2(xs[(k2 + 8) * 128 + M0],     xs[(k2 + 9) * 128 + M0],     h.z, l.z);
        split2(xs[(k2 + 8) * 128 + M0 + 8], xs[(k2 + 9) * 128 + M0 + 8], h.w, l.w);
        dh[o] = h;
        dl[o] = l;
    }
}

// pack emb into fp16 hi/lo fragment-order B chunks: c = kt*8+ch
__global__ void packB_kernel(const float* __restrict__ emb) {
    const int c = blockIdx.x;
    const int kt = c >> 3, ch = c & 7;
    const int k0 = kt * 128, d0 = ch * 32;
    const int tid = threadIdx.x;
    uint2* dh = (uint2*)g_pBh + (size_t)c * 1024;
    uint2* dl = (uint2*)g_pBl + (size_t)c * 1024;
#pragma unroll
    for (int i = 0; i < 4; ++i) {
        int o = tid + i * 256;                  // [g][n][tig], 1024 total
        int tig = o & 3, n = (o >> 2) & 127, g = o >> 9;
        int k2 = d0 + g * 16 + 2 * tig;
        uint2 h, l;
        split2(emb[(size_t)k2 * K_DIM + k0 + n],       emb[(size_t)(k2 + 1) * K_DIM + k0 + n], h.x, l.x);
        split2(emb[(size_t)(k2 + 8) * K_DIM + k0 + n], emb[(size_t)(k2 + 9) * K_DIM + k0 + n], h.y, l.y);
        dh[o] = h;
        dl[o] = l;
    }
}

// ---------------- main kernel ----------------
__global__ __launch_bounds__(THREADS, 2)
void vq_mma_kernel(const float* __restrict__ emb, float* __restrict__ out,
                   float* __restrict__ idx_out, int has_idx) {
    extern __shared__ char smc[];
    __shared__ float e2s[K_DIM];
    __shared__ float redv[BMC][4];
    __shared__ int redi[BMC][4];
    __shared__ int idx_s[BMC];

    const int tid = threadIdx.x;
    const int wid = tid >> 5;
    const int lane = tid & 31;
    const int gid = lane >> 2;
    const int tig = lane & 3;
    const int wm = wid >> 2;          // 0..1 (M)
    const int wn = wid & 3;           // 0..3 (N)
    const int mbw = wm * 32;
    const int nbw = wn * 32;
    const uint32_t smb = smem_u32(smc);

    const int n0 = blockIdx.x * BMC;
    const int tile128 = blockIdx.x >> 1;      // packed A tile
    const int half = blockIdx.x & 1;          // which 64-row half
    const int b = n0 >> 10;
    const int hw0 = n0 & 1023;

    // staging: chunk c -> buffer c%3; A-half slice + full B, 6 cp16/thread
    auto stage = [&](int c) {
        const uint32_t base = smb + (uint32_t)(c % 3) * BUF_BYTES;
        const uint4* sAh = (const uint4*)g_pAh + (size_t)(tile128 * 8 + (c & 7)) * 512;
        const uint4* sAl = (const uint4*)g_pAl + (size_t)(tile128 * 8 + (c & 7)) * 512;
        const uint4* sBh = (const uint4*)g_pBh + (size_t)c * 512;
        const uint4* sBl = (const uint4*)g_pBl + (size_t)c * 512;
        {   // A: 256 uint4 per array (g in {0,1}, 128 each from the half slice)
            int g = tid >> 7;
            int off = g * 256 + half * 128 + (tid & 127);
            cp16(base + tid * 16, sAh + off);
            cp16(base + A_BYTES + tid * 16, sAl + off);
        }
#pragma unroll
        for (int i = 0; i < 2; ++i) {   // B: 512 uint4 per array
            int t = tid + i * 256;
            cp16(base + 2 * A_BYTES + t * 16, sBh + t);
            cp16(base + 2 * A_BYTES + B_BYTES + t * 16, sBl + t);
        }
    };

    for (int i = tid; i < K_DIM; i += THREADS) e2s[i] = g_e2[i];

    float best[4];
    int bidx[4];
#pragma unroll
    for (int s = 0; s < 4; ++s) { best[s] = CUDART_INF_F; bidx[s] = 0; }

    stage(0); CP_COMMIT();
    stage(1); CP_COMMIT();

    float acc[2][4][4];
    // local A fragment indices within the 64-row half ([g][mp' 0..31][tig])
    const int Ml0 = mbw + gid;                         // mt=0 row
    const int mp0 = ((Ml0 >> 1) & 0x18) | (Ml0 & 7);
    const int a0i = mp0 * 4 + tig;
    const int a1i = a0i + 32;                          // mt=1 row = Ml0+16
    const int bbase = (nbw + gid) * 4 + tig;

    for (int c = 0; c < NCHUNK; ++c) {
        if ((c & 7) == 0) {
#pragma unroll
            for (int mt = 0; mt < 2; ++mt)
#pragma unroll
                for (int nt = 0; nt < 4; ++nt)
#pragma unroll
                    for (int j = 0; j < 4; ++j) acc[mt][nt][j] = 0.f;
        }

        if (c < NCHUNK - 1) { CP_WAIT(1); } else { CP_WAIT(0); }
        __syncthreads();
        if (c + 2 < NCHUNK) { stage(c + 2); CP_COMMIT(); }

        const char* buf = smc + (c % 3) * BUF_BYTES;
        const uint4* Ah = (const uint4*)buf;
        const uint4* Al = (const uint4*)(buf + A_BYTES);
        const uint2* Bh = (const uint2*)(buf + 2 * A_BYTES);
        const uint2* Bl = (const uint2*)(buf + 2 * A_BYTES + B_BYTES);

#pragma unroll
        for (int g = 0; g < 2; ++g) {
            uint4 ah0 = Ah[g * 128 + a0i];
            uint4 ah1 = Ah[g * 128 + a1i];
            uint4 al0 = Al[g * 128 + a0i];
            uint4 al1 = Al[g * 128 + a1i];
#pragma unroll
            for (int nt = 0; nt < 4; ++nt) {
                uint2 bh = Bh[g * 512 + bbase + nt * 32];
                uint2 bl = Bl[g * 512 + bbase + nt * 32];
                mma16(acc[0][nt], ah0, bh);
                mma16(acc[0][nt], ah0, bl);
                mma16(acc[0][nt], al0, bh);
                mma16(acc[1][nt], ah1, bh);
                mma16(acc[1][nt], ah1, bl);
                mma16(acc[1][nt], al1, bh);
            }
        }

        if ((c & 7) == 7) {
            // fused argmin epilogue for k-tile kt = c>>3 (registers only)
            const int k0 = (c >> 3) * 128;
#pragma unroll
            for (int mt = 0; mt < 2; ++mt) {
#pragma unroll
                for (int nt = 0; nt < 4; ++nt) {
                    const int kc = k0 + nbw + nt * 8 + 2 * tig;
                    const float e20 = e2s[kc], e21 = e2s[kc + 1];
                    float s0 = fmaf(-2.f, acc[mt][nt][0], e20);
                    float s1 = fmaf(-2.f, acc[mt][nt][1], e21);
                    float s2 = fmaf(-2.f, acc[mt][nt][2], e20);
                    float s3 = fmaf(-2.f, acc[mt][nt][3], e21);
                    if (s0 < best[2 * mt]) { best[2 * mt] = s0; bidx[2 * mt] = kc; }
                    if (s1 < best[2 * mt]) { best[2 * mt] = s1; bidx[2 * mt] = kc + 1; }
                    if (s2 < best[2 * mt + 1]) { best[2 * mt + 1] = s2; bidx[2 * mt + 1] = kc; }
                    if (s3 < best[2 * mt + 1]) { best[2 * mt + 1] = s3; bidx[2 * mt + 1] = kc + 1; }
                }
            }
        }
    }

    // reduce across the 4 lanes of each quad (same rows, different cols)
#pragma unroll
    for (int s = 0; s < 4; ++s) {
        float v = best[s];
        int ix = bidx[s];
#pragma unroll
        for (int off = 1; off <= 2; off <<= 1) {
            float v2 = __shfl_xor_sync(0xFFFFFFFFu, v, off);
            int i2 = __shfl_xor_sync(0xFFFFFFFFu, ix, off);
            if (v2 < v || (v2 == v && i2 < ix)) { v = v2; ix = i2; }
        }
        if (tig == 0) {
            int row = mbw + (s >> 1) * 16 + gid + (s & 1) * 8;
            redv[row][wn] = v;
            redi[row][wn] = ix;
        }
    }
    __syncthreads();
    if (tid < BMC) {
        float bv = redv[tid][0];
        int bi = redi[tid][0];
#pragma unroll
        for (int t = 1; t < 4; ++t) {
            float v = redv[tid][t];
            int id = redi[tid][t];
            if (v < bv || (v == bv && id < bi)) { bv = v; bi = id; }
        }
        idx_s[tid] = bi;
        if (has_idx) idx_out[n0 + tid] = (float)bi;
    }
    __syncthreads();

    // gather nearest code (exact fp32), scatter to (B,D,H,W)
    for (int r = tid; r < D_DIM * BMC; r += THREADS) {
        int d = r >> 6;
        int m = r & (BMC - 1);
        out[((size_t)b * D_DIM + d) * 1024 + hw0 + m] = emb[(size_t)d * K_DIM + idx_s[m]];
    }
}

extern "C" void kernel_launch(void* const* d_in, const int* in_sizes, int n_in,
                              void* d_out, int out_size) {
    const float* x = (const float*)d_in[0];    // (64,256,32,32)
    const float* emb = (const float*)d_in[1];  // (256,1024)
    float* out = (float*)d_out;

    const int n_img = 64 * 256 * 32 * 32;
    const int n_lat = 64 * 32 * 32;
    float* idx_out = nullptr;
    int has_idx = 0;
    if (out_size >= n_img + n_lat) {
        idx_out = out + n_img;
        has_idx = 1;
    }

    cudaFuncSetAttribute(vq_mma_kernel, cudaFuncAttributeMaxDynamicSharedMemorySize, SMEM_DYN);

    e2_kernel<<<4, 256>>>(emb);
    packA_kernel<<<dim3(8, 512), 256>>>(x);
    packB_kernel<<<64, 256>>>(emb);
    vq_mma_kernel<<<1024, THREADS, SMEM_DYN>>>(emb, out, idx_out, has_idx);
}